// round 7
// baseline (speedup 1.0000x reference)
#include <cuda_runtime.h>
#include <cuda_bf16.h>

// Soft quantizer forward (levels = linspace(-2,2,25), uniform):
//   x_ste == x_hard == -2 + rint((x+2)*6)/6,  symbols = rint((x+2)*6).
//
// Byte-bound kernel: 24 MB read + 72 MB write are mandatory. Plateau across
// R2-R6 sweeps (occ 38-73%, MLP 1-8, grid 768-6144) pins the bound on the
// store path (~4.8 TB/s write). This round: identical best shape (1 float4 /
// thread, exact cover, 6144x256) + evict-first stores (__stcs) so dirty
// output lines drain promptly and the input stays L2-resident across graph
// replays.

__device__ __forceinline__ float4 quant_h(float4 v, float4* s) {
    const float STEP = 0.16666667f;   // 1/6
    float r0 = rintf(fminf(fmaxf(fmaf(v.x, 6.0f, 12.0f), 0.0f), 24.0f));
    float r1 = rintf(fminf(fmaxf(fmaf(v.y, 6.0f, 12.0f), 0.0f), 24.0f));
    float r2 = rintf(fminf(fmaxf(fmaf(v.z, 6.0f, 12.0f), 0.0f), 24.0f));
    float r3 = rintf(fminf(fmaxf(fmaf(v.w, 6.0f, 12.0f), 0.0f), 24.0f));
    *s = make_float4(r0, r1, r2, r3);
    return make_float4(fmaf(r0, STEP, -2.0f), fmaf(r1, STEP, -2.0f),
                       fmaf(r2, STEP, -2.0f), fmaf(r3, STEP, -2.0f));
}

// Exact-cover fast path: grid*block == n4, 3 output tensors.
__global__ void __launch_bounds__(256, 8)
softquant_exact(const float4* __restrict__ x4,
                float4* __restrict__ o0,
                float4* __restrict__ o1,
                float4* __restrict__ o2) {
    int i = blockIdx.x * 256 + threadIdx.x;
    float4 v = __ldg(&x4[i]);          // default policy: keep input resident
    float4 s4;
    float4 h4 = quant_h(v, &s4);
    __stcs(&o0[i], h4);                // x_ste (forward == x_hard), evict-first
    __stcs(&o1[i], h4);                // x_hard
    __stcs(&o2[i], s4);                // symbols (as float)
}

// Generic fallback for any other shape / output packing.
__global__ void __launch_bounds__(256)
softquant_generic(const float4* __restrict__ x4,
                  float4* __restrict__ o0,
                  float4* __restrict__ o1,
                  float4* __restrict__ o2,
                  int n4, int nblocks) {
    int i = blockIdx.x * blockDim.x + threadIdx.x;
    if (i >= n4) return;
    float4 s4;
    float4 h4 = quant_h(x4[i], &s4);
    o0[i] = h4;
    if (nblocks >= 2) o1[i] = h4;
    if (nblocks >= 3) o2[i] = s4;
}

extern "C" void kernel_launch(void* const* d_in, const int* in_sizes, int n_in,
                              void* d_out, int out_size) {
    const float* x = (const float*)d_in[0];
    float* out     = (float*)d_out;

    int n  = in_sizes[0];
    int n4 = n / 4;                     // 1,572,864 for the bench shape

    int nblocks = out_size / n;         // packed output tensors (expect 3)
    if (nblocks < 1) nblocks = 1;
    if (nblocks > 3) nblocks = 3;

    const float4* x4 = (const float4*)x;
    float4* o0 = (float4*)out;
    float4* o1 = (float4*)(out + (size_t)n);
    float4* o2 = (float4*)(out + 2 * (size_t)n);

    if ((n % 4 == 0) && (n4 % 256 == 0) && nblocks == 3) {
        softquant_exact<<<n4 / 256, 256>>>(x4, o0, o1, o2);   // 6144 blocks
    } else {
        int blocks = (n4 + 255) / 256;
        softquant_generic<<<blocks, 256>>>(x4, o0, o1, o2, n4, nblocks);
    }
}

// round 8
// speedup vs baseline: 1.2243x; 1.2243x over previous
#include <cuda_runtime.h>
#include <cuda_bf16.h>

// Soft quantizer forward (levels = linspace(-2,2,25), uniform):
//   x_ste == x_hard == -2 + rint((x+2)*6)/6,  symbols = rint((x+2)*6).
//
// FINAL / CONVERGED. The forward pass of the straight-through estimator is
// exactly the hard quantization, so the softmax pipeline is dead code; with
// uniform levels the argmin is closed-form. What remains is a mandatory
// 24 MB read + 72 MB write stream. Measured plateau (R2-R6: occ 38-73%,
// MLP 1-8, grid 768-6144, all within 14.7-16.0 us) sits at the store-path
// throughput ceiling (~4.8 TB/s on the 72 MB write side). Cache-policy
// stores (__stcs) measurably regress (R7: +40%) - default write-back is
// optimal. Best shape: 1 float4/thread, exact-cover grid, 4x128-bit memory
// ops/thread, default policies.

__device__ __forceinline__ float4 quant_h(float4 v, float4* s) {
    const float STEP = 0.16666667f;   // 1/6
    float r0 = rintf(fminf(fmaxf(fmaf(v.x, 6.0f, 12.0f), 0.0f), 24.0f));
    float r1 = rintf(fminf(fmaxf(fmaf(v.y, 6.0f, 12.0f), 0.0f), 24.0f));
    float r2 = rintf(fminf(fmaxf(fmaf(v.z, 6.0f, 12.0f), 0.0f), 24.0f));
    float r3 = rintf(fminf(fmaxf(fmaf(v.w, 6.0f, 12.0f), 0.0f), 24.0f));
    *s = make_float4(r0, r1, r2, r3);
    return make_float4(fmaf(r0, STEP, -2.0f), fmaf(r1, STEP, -2.0f),
                       fmaf(r2, STEP, -2.0f), fmaf(r3, STEP, -2.0f));
}

// Exact-cover fast path: grid*block == n4, 3 output tensors, default stores.
__global__ void __launch_bounds__(256, 8)
softquant_exact(const float4* __restrict__ x4,
                float4* __restrict__ o0,
                float4* __restrict__ o1,
                float4* __restrict__ o2) {
    int i = blockIdx.x * 256 + threadIdx.x;
    float4 s4;
    float4 h4 = quant_h(x4[i], &s4);
    o0[i] = h4;      // x_ste (forward == x_hard)
    o1[i] = h4;      // x_hard
    o2[i] = s4;      // symbols (as float)
}

// Generic fallback for any other shape / output packing.
__global__ void __launch_bounds__(256)
softquant_generic(const float4* __restrict__ x4,
                  float4* __restrict__ o0,
                  float4* __restrict__ o1,
                  float4* __restrict__ o2,
                  int n4, int nblocks) {
    int i = blockIdx.x * blockDim.x + threadIdx.x;
    if (i >= n4) return;
    float4 s4;
    float4 h4 = quant_h(x4[i], &s4);
    o0[i] = h4;
    if (nblocks >= 2) o1[i] = h4;
    if (nblocks >= 3) o2[i] = s4;
}

extern "C" void kernel_launch(void* const* d_in, const int* in_sizes, int n_in,
                              void* d_out, int out_size) {
    const float* x = (const float*)d_in[0];
    float* out     = (float*)d_out;

    int n  = in_sizes[0];
    int n4 = n / 4;                     // 1,572,864 for the bench shape

    int nblocks = out_size / n;         // packed output tensors (expect 3)
    if (nblocks < 1) nblocks = 1;
    if (nblocks > 3) nblocks = 3;

    const float4* x4 = (const float4*)x;
    float4* o0 = (float4*)out;
    float4* o1 = (float4*)(out + (size_t)n);
    float4* o2 = (float4*)(out + 2 * (size_t)n);

    if ((n % 4 == 0) && (n4 % 256 == 0) && nblocks == 3) {
        softquant_exact<<<n4 / 256, 256>>>(x4, o0, o1, o2);   // 6144 blocks
    } else {
        int blocks = (n4 + 255) / 256;
        softquant_generic<<<blocks, 256>>>(x4, o0, o1, o2, n4, nblocks);
    }
}

// round 9
// speedup vs baseline: 1.2429x; 1.0152x over previous
#include <cuda_runtime.h>
#include <cuda_bf16.h>

// Soft quantizer forward (levels = linspace(-2,2,25), uniform):
//   x_ste == x_hard == -2 + rint((x+2)*6)/6,  symbols = rint((x+2)*6).
//
// FINAL / CONVERGED. Forward pass of the straight-through estimator equals
// the hard quantization (softmax pipeline is dead code in the forward value);
// uniform levels make the argmin closed-form. Remaining work is a mandatory
// 24 MB read + 72 MB write stream, measured pinned at the L2 write-path
// ceiling (~4.8 TB/s store side, ~6.4 TB/s blended) across 8 rounds of
// sweeps (occ 38-73%, MLP 1-8, grid 768-6144; .cs hints regress +40%).
// Shape: 1 float4 per thread, exact-cover grid, 4x128-bit memory ops/thread,
// default cache policy.

__device__ __forceinline__ float4 quant_h(float4 v, float4* s) {
    const float STEP = 0.16666667f;   // 1/6
    float r0 = rintf(fminf(fmaxf(fmaf(v.x, 6.0f, 12.0f), 0.0f), 24.0f));
    float r1 = rintf(fminf(fmaxf(fmaf(v.y, 6.0f, 12.0f), 0.0f), 24.0f));
    float r2 = rintf(fminf(fmaxf(fmaf(v.z, 6.0f, 12.0f), 0.0f), 24.0f));
    float r3 = rintf(fminf(fmaxf(fmaf(v.w, 6.0f, 12.0f), 0.0f), 24.0f));
    *s = make_float4(r0, r1, r2, r3);
    return make_float4(fmaf(r0, STEP, -2.0f), fmaf(r1, STEP, -2.0f),
                       fmaf(r2, STEP, -2.0f), fmaf(r3, STEP, -2.0f));
}

// Exact-cover fast path: grid*block == n4, 3 output tensors, default stores.
__global__ void __launch_bounds__(512, 4)
softquant_exact(const float4* __restrict__ x4,
                float4* __restrict__ o0,
                float4* __restrict__ o1,
                float4* __restrict__ o2) {
    int i = blockIdx.x * 512 + threadIdx.x;
    float4 s4;
    float4 h4 = quant_h(x4[i], &s4);
    o0[i] = h4;      // x_ste (forward == x_hard)
    o1[i] = h4;      // x_hard
    o2[i] = s4;      // symbols (as float)
}

// Generic fallback for any other shape / output packing.
__global__ void __launch_bounds__(256)
softquant_generic(const float4* __restrict__ x4,
                  float4* __restrict__ o0,
                  float4* __restrict__ o1,
                  float4* __restrict__ o2,
                  int n4, int nblocks) {
    int i = blockIdx.x * blockDim.x + threadIdx.x;
    if (i >= n4) return;
    float4 s4;
    float4 h4 = quant_h(x4[i], &s4);
    o0[i] = h4;
    if (nblocks >= 2) o1[i] = h4;
    if (nblocks >= 3) o2[i] = s4;
}

extern "C" void kernel_launch(void* const* d_in, const int* in_sizes, int n_in,
                              void* d_out, int out_size) {
    const float* x = (const float*)d_in[0];
    float* out     = (float*)d_out;

    int n  = in_sizes[0];
    int n4 = n / 4;                     // 1,572,864 for the bench shape

    int nblocks = out_size / n;         // packed output tensors (expect 3)
    if (nblocks < 1) nblocks = 1;
    if (nblocks > 3) nblocks = 3;

    const float4* x4 = (const float4*)x;
    float4* o0 = (float4*)out;
    float4* o1 = (float4*)(out + (size_t)n);
    float4* o2 = (float4*)(out + 2 * (size_t)n);

    if ((n % 4 == 0) && (n4 % 512 == 0) && nblocks == 3) {
        softquant_exact<<<n4 / 512, 512>>>(x4, o0, o1, o2);   // 3072 blocks
    } else {
        int blocks = (n4 + 255) / 256;
        softquant_generic<<<blocks, 256>>>(x4, o0, o1, o2, n4, nblocks);
    }
}